// round 15
// baseline (speedup 1.0000x reference)
#include <cuda_runtime.h>
#include <cstdint>

// ---------------------------------------------------------------------------
// Problem constants
//   B=4, NR=512, NA=64, TDIM=1024, DDIM=128, HID=32, INT=128
//   outer: [B,NR,NA,INT] = 16,777,216 f32 ; mask: [B,NR,NA] = 131,072 f32
// ---------------------------------------------------------------------------
#define B_      4
#define NR_     512
#define NA_     64
#define TDIM_   1024
#define DDIM_   128
#define HID_    32
#define INTD_   128

// Scratch (allocation-free rule: __device__ globals)
__device__ float g_tf[B_ * NR_ * HID_];            // 65536
__device__ float g_df[B_ * NA_ * HID_];            // 8192
__device__ float g_G [B_ * NA_ * INTD_ * HID_];    // 1,048,576 (4 MB)

// ---------------------------------------------------------------------------
// Kernel A: layernorm(target) @ W_t^T + b_t, * tmask  ->  g_tf [B*NR, 32]
// 64 blocks x 128 threads; each block does 32 rows, K=1024 in 128-chunks.
// ---------------------------------------------------------------------------
__global__ void tf_kernel(const float* __restrict__ X,
                          const float* __restrict__ tmask,
                          const float* __restrict__ gam,
                          const float* __restrict__ bet,
                          const float* __restrict__ W,
                          const float* __restrict__ bt)
{
    __shared__ float mu_s[32], rs_s[32];
    __shared__ float Xs[32][129];
    __shared__ float Ws[32][129];

    const int tid  = threadIdx.x;      // 128
    const int lane = tid & 31;
    const int wid  = tid >> 5;         // 4 warps
    const int row0 = blockIdx.x * 32;

    // ---- per-row LN stats (each warp: 8 rows) ----
    for (int j = 0; j < 8; j++) {
        const int ri = wid * 8 + j;
        const float* xr = X + (size_t)(row0 + ri) * TDIM_;
        float s = 0.f, ss = 0.f;
        #pragma unroll 8
        for (int q = 0; q < 32; q++) {
            float v = xr[lane + q * 32];
            s += v; ss += v * v;
        }
        for (int o = 16; o; o >>= 1) {
            s  += __shfl_xor_sync(0xffffffffu, s,  o);
            ss += __shfl_xor_sync(0xffffffffu, ss, o);
        }
        if (lane == 0) {
            float m   = s * (1.f / 1024.f);
            float var = ss * (1.f / 1024.f) - m * m;
            mu_s[ri] = m;
            rs_s[ri] = rsqrtf(var + 1e-5f);
        }
    }
    __syncthreads();

    const int r0 = (tid >> 3) * 2;     // 0..30 step 2
    const int h0 = (tid & 7) * 4;      // 0..28 step 4
    float acc[2][4] = {};

    for (int kc = 0; kc < TDIM_; kc += 128) {
        __syncthreads();
        // normalized X tile (coalesced global, conflict-free STS)
        for (int idx = tid; idx < 4096; idx += 128) {
            int ri = idx >> 7, k = idx & 127;
            float v = X[(size_t)(row0 + ri) * TDIM_ + kc + k];
            Xs[ri][k] = (v - mu_s[ri]) * rs_s[ri] * gam[kc + k] + bet[kc + k];
        }
        // W tile
        for (int idx = tid; idx < 4096; idx += 128) {
            int h = idx >> 7, k = idx & 127;
            Ws[h][k] = W[h * TDIM_ + kc + k];
        }
        __syncthreads();

        #pragma unroll 8
        for (int k = 0; k < 128; k++) {
            float a0 = Xs[r0][k];
            float a1 = Xs[r0 + 1][k];
            #pragma unroll
            for (int j = 0; j < 4; j++) {
                float w = Ws[h0 + j][k];
                acc[0][j] += a0 * w;
                acc[1][j] += a1 * w;
            }
        }
    }

    #pragma unroll
    for (int rr = 0; rr < 2; rr++) {
        int row = row0 + r0 + rr;
        float tm = tmask[row];
        float4 o;
        o.x = (acc[rr][0] + bt[h0 + 0]) * tm;
        o.y = (acc[rr][1] + bt[h0 + 1]) * tm;
        o.z = (acc[rr][2] + bt[h0 + 2]) * tm;
        o.w = (acc[rr][3] + bt[h0 + 3]) * tm;
        *reinterpret_cast<float4*>(&g_tf[row * HID_ + h0]) = o;
    }
}

// ---------------------------------------------------------------------------
// Kernel B: layernorm(drug) @ W_d^T + b_d, * dmask  ->  g_df [B*NA, 32]
// 256 blocks (one per row) x 128 threads.
// ---------------------------------------------------------------------------
__global__ void df_kernel(const float* __restrict__ X,
                          const float* __restrict__ dmask,
                          const float* __restrict__ gam,
                          const float* __restrict__ bet,
                          const float* __restrict__ W,
                          const float* __restrict__ bd)
{
    const int row = blockIdx.x;
    const int tid = threadIdx.x;
    __shared__ float xn[128];
    __shared__ float red[8];

    float v = X[row * DDIM_ + tid];
    float s = v, ss = v * v;
    for (int o = 16; o; o >>= 1) {
        s  += __shfl_xor_sync(0xffffffffu, s,  o);
        ss += __shfl_xor_sync(0xffffffffu, ss, o);
    }
    if ((tid & 31) == 0) { red[tid >> 5] = s; red[4 + (tid >> 5)] = ss; }
    __syncthreads();
    float sum = red[0] + red[1] + red[2] + red[3];
    float sq  = red[4] + red[5] + red[6] + red[7];
    float mu  = sum * (1.f / 128.f);
    float var = sq * (1.f / 128.f) - mu * mu;
    float rs  = rsqrtf(var + 1e-5f);
    xn[tid] = (v - mu) * rs * gam[tid] + bet[tid];
    __syncthreads();

    const int wid = tid >> 5, lane = tid & 31;
    const float dm = dmask[row];
    #pragma unroll
    for (int j = 0; j < 8; j++) {
        int h = wid * 8 + j;
        float acc = 0.f;
        #pragma unroll
        for (int q = 0; q < 4; q++)
            acc += xn[lane + q * 32] * W[h * DDIM_ + lane + q * 32];
        for (int o = 16; o; o >>= 1)
            acc += __shfl_xor_sync(0xffffffffu, acc, o);
        if (lane == 0) g_df[row * HID_ + h] = (acc + bd[h]) * dm;
    }
}

// ---------------------------------------------------------------------------
// Kernel C: G[b,m,i,c] = sum_e df[b,m,e] * W_out[i, c*32+e]
// grid (16 i-chunks of 8, 4 b) x 256 threads.
// ---------------------------------------------------------------------------
__global__ void g_kernel(const float* __restrict__ Wout)
{
    const int i0 = blockIdx.x * 8;
    const int b  = blockIdx.y;
    __shared__ float dfT[32][64];        // [e][m]
    __shared__ float Wc[8][1024];
    const int tid = threadIdx.x;

    for (int idx = tid; idx < 2048; idx += 256) {
        int e = idx >> 6, m = idx & 63;
        dfT[e][m] = g_df[(b * NA_ + m) * HID_ + e];
    }
    for (int idx = tid; idx < 8192; idx += 256) {
        int ii = idx >> 10, k = idx & 1023;
        Wc[ii][k] = Wout[(i0 + ii) * 1024 + k];
    }
    __syncthreads();

    const int m0 = (tid & 15) * 4;
    const int pr = tid >> 4;
    for (int it = 0; it < 16; it++) {
        int ic = it * 16 + pr;
        int i = ic >> 5, c = ic & 31;
        const float* wrow = &Wc[i][c * 32];
        float4 acc = {0.f, 0.f, 0.f, 0.f};
        #pragma unroll
        for (int e = 0; e < 32; e++) {
            float w = wrow[e];
            float4 d = *reinterpret_cast<const float4*>(&dfT[e][m0]);
            acc.x += w * d.x; acc.y += w * d.y;
            acc.z += w * d.z; acc.w += w * d.w;
        }
        size_t base = ((size_t)((b * NA_ + m0) * INTD_ + (i0 + i))) * HID_ + c;
        const size_t mstep = (size_t)INTD_ * HID_;   // 4096
        g_G[base]             = acc.x;
        g_G[base + mstep]     = acc.y;
        g_G[base + 2 * mstep] = acc.z;
        g_G[base + 3 * mstep] = acc.w;
    }
}

// ---------------------------------------------------------------------------
// Kernel D: main contraction with packed fp32x2 FMA.
//   out[b,n,m,i] = (sum_c tf[b,n,c]*G[b,m,i,c] + b_out[i]) * tmask[b,n]*dmask[b,m]
// grid (8 n-tiles, 64 m, 4 b) x 256 threads. Block tile 64n x 128i, K=32.
// Thread tile 8n x 4i; n-pairs packed into f32x2 lanes.
// ---------------------------------------------------------------------------
__global__ void __launch_bounds__(256) outer_kernel(
    const float* __restrict__ bout,
    const float* __restrict__ tmask,
    const float* __restrict__ dmask,
    float* __restrict__ out,
    float* __restrict__ mask_out)
{
    const int nt = blockIdx.x, m = blockIdx.y, b = blockIdx.z;
    const int nblk = nt * 64;

    __shared__ __align__(16) float tf_s[32][68];   // [c][n], padded
    __shared__ float G_s[32][132];                 // [c][i], padded
    __shared__ float bout_s[128];

    const int tid = threadIdx.x;

    for (int idx = tid; idx < 2048; idx += 256) {
        int n = idx >> 5, c = idx & 31;
        tf_s[c][n] = g_tf[(b * NR_ + nblk + n) * HID_ + c];
    }
    {
        const float* Gm = g_G + (size_t)(b * NA_ + m) * (INTD_ * HID_);
        for (int idx = tid; idx < 4096; idx += 256) {
            int i = idx >> 5, c = idx & 31;
            G_s[c][i] = Gm[idx];
        }
    }
    if (tid < 128) bout_s[tid] = bout[tid];
    __syncthreads();

    const int tn = tid >> 5;        // 0..7  -> n-group of 8
    const int ti = tid & 31;        // i base; i = ti + 32*j
    const int n0 = tn * 8;

    unsigned long long acc[4][4] = {};   // [n-pair p][i j] packed f32x2

    #pragma unroll
    for (int c = 0; c < 32; c++) {
        const ulonglong2 A0 = *reinterpret_cast<const ulonglong2*>(&tf_s[c][n0]);
        const ulonglong2 A1 = *reinterpret_cast<const ulonglong2*>(&tf_s[c][n0 + 4]);
        unsigned long long a[4];
        a[0] = A0.x; a[1] = A0.y; a[2] = A1.x; a[3] = A1.y;

        unsigned long long gg[4];
        #pragma unroll
        for (int j = 0; j < 4; j++) {
            unsigned gu = __float_as_uint(G_s[c][ti + 32 * j]);
            asm("mov.b64 %0, {%1, %1};" : "=l"(gg[j]) : "r"(gu));
        }
        #pragma unroll
        for (int p = 0; p < 4; p++) {
            #pragma unroll
            for (int j = 0; j < 4; j++) {
                asm("fma.rn.f32x2 %0, %1, %2, %0;"
                    : "+l"(acc[p][j]) : "l"(a[p]), "l"(gg[j]));
            }
        }
    }

    // epilogue: bias + mask + store (coalesced along i)
    const float dm = dmask[b * NA_ + m];
    #pragma unroll
    for (int p = 0; p < 4; p++) {
        const int n_lo = nblk + n0 + 2 * p;
        const float f_lo = tmask[b * NR_ + n_lo] * dm;
        const float f_hi = tmask[b * NR_ + n_lo + 1] * dm;
        const size_t base_lo = ((size_t)((b * NR_ + n_lo) * NA_ + m)) << 7;  // *128
        const size_t base_hi = base_lo + ((size_t)NA_ << 7);                  // next n
        #pragma unroll
        for (int j = 0; j < 4; j++) {
            unsigned rlo, rhi;
            asm("mov.b64 {%0, %1}, %2;" : "=r"(rlo), "=r"(rhi) : "l"(acc[p][j]));
            const int i = ti + 32 * j;
            out[base_lo + i] = (__uint_as_float(rlo) + bout_s[i]) * f_lo;
            out[base_hi + i] = (__uint_as_float(rhi) + bout_s[i]) * f_hi;
        }
    }

    // mask output (second tuple element), each (b,n,m) written exactly once
    if (mask_out != nullptr && tid < 64) {
        const int n = nblk + tid;
        mask_out[(size_t)(b * NR_ + n) * NA_ + m] = tmask[b * NR_ + n] * dm;
    }
}

// ---------------------------------------------------------------------------
// launch
// ---------------------------------------------------------------------------
extern "C" void kernel_launch(void* const* d_in, const int* in_sizes, int n_in,
                              void* d_out, int out_size)
{
    const float* target = (const float*)d_in[0];   // [4,512,1024]
    const float* drug   = (const float*)d_in[1];   // [4,64,128]
    const float* tmask  = (const float*)d_in[2];   // [4,512]
    const float* dmask  = (const float*)d_in[3];   // [4,64]
    const float* ln_t_g = (const float*)d_in[4];
    const float* ln_t_b = (const float*)d_in[5];
    const float* ln_d_g = (const float*)d_in[6];
    const float* ln_d_b = (const float*)d_in[7];
    const float* W_t    = (const float*)d_in[8];   // [32,1024]
    const float* b_t    = (const float*)d_in[9];
    const float* W_d    = (const float*)d_in[10];  // [32,128]
    const float* b_d    = (const float*)d_in[11];
    const float* W_out  = (const float*)d_in[12];  // [128,1024]
    const float* b_out  = (const float*)d_in[13];

    float* outer = (float*)d_out;
    const long long OUTER_ELEMS = (long long)B_ * NR_ * NA_ * INTD_;  // 16,777,216
    const long long MASK_ELEMS  = (long long)B_ * NR_ * NA_;          // 131,072
    float* maskp = (out_size >= (int)(OUTER_ELEMS + MASK_ELEMS))
                       ? outer + OUTER_ELEMS : nullptr;

    tf_kernel<<<64, 128>>>(target, tmask, ln_t_g, ln_t_b, W_t, b_t);
    df_kernel<<<256, 128>>>(drug, dmask, ln_d_g, ln_d_b, W_d, b_d);
    g_kernel<<<dim3(16, 4), 256>>>(W_out);
    outer_kernel<<<dim3(8, 64, 4), 256>>>(b_out, tmask, dmask, outer, maskp);
}

// round 16
// speedup vs baseline: 1.0272x; 1.0272x over previous
#include <cuda_runtime.h>
#include <cstdint>

// ---------------------------------------------------------------------------
// Problem constants
//   B=4, NR=512, NA=64, TDIM=1024, DDIM=128, HID=32, INT=128
//   outer: [B,NR,NA,INT] = 16,777,216 f32 ; mask: [B,NR,NA] = 131,072 f32
// ---------------------------------------------------------------------------
#define B_      4
#define NR_     512
#define NA_     64
#define TDIM_   1024
#define DDIM_   128
#define HID_    32
#define INTD_   128

// Scratch (allocation-free rule: __device__ globals)
__device__ float g_tf[B_ * NR_ * HID_];            // 65536
__device__ float g_df[B_ * NA_ * HID_];            // 8192
__device__ float g_G [B_ * NA_ * INTD_ * HID_];    // 1,048,576 (4 MB)

// ---------------------------------------------------------------------------
// Kernel A: layernorm(target) @ W_t^T + b_t, * tmask  ->  g_tf [B*NR, 32]
// 64 blocks x 128 threads; each block does 32 rows, K=1024 in 128-chunks.
// ---------------------------------------------------------------------------
__global__ void tf_kernel(const float* __restrict__ X,
                          const float* __restrict__ tmask,
                          const float* __restrict__ gam,
                          const float* __restrict__ bet,
                          const float* __restrict__ W,
                          const float* __restrict__ bt)
{
    __shared__ float mu_s[32], rs_s[32];
    __shared__ float Xs[32][129];
    __shared__ float Ws[32][129];

    const int tid  = threadIdx.x;      // 128
    const int lane = tid & 31;
    const int wid  = tid >> 5;         // 4 warps
    const int row0 = blockIdx.x * 32;

    // ---- per-row LN stats (each warp: 8 rows) ----
    for (int j = 0; j < 8; j++) {
        const int ri = wid * 8 + j;
        const float* xr = X + (size_t)(row0 + ri) * TDIM_;
        float s = 0.f, ss = 0.f;
        #pragma unroll 8
        for (int q = 0; q < 32; q++) {
            float v = xr[lane + q * 32];
            s += v; ss += v * v;
        }
        for (int o = 16; o; o >>= 1) {
            s  += __shfl_xor_sync(0xffffffffu, s,  o);
            ss += __shfl_xor_sync(0xffffffffu, ss, o);
        }
        if (lane == 0) {
            float m   = s * (1.f / 1024.f);
            float var = ss * (1.f / 1024.f) - m * m;
            mu_s[ri] = m;
            rs_s[ri] = rsqrtf(var + 1e-5f);
        }
    }
    __syncthreads();

    const int r0 = (tid >> 3) * 2;     // 0..30 step 2
    const int h0 = (tid & 7) * 4;      // 0..28 step 4
    float acc[2][4] = {};

    for (int kc = 0; kc < TDIM_; kc += 128) {
        __syncthreads();
        // normalized X tile (coalesced global, conflict-free STS)
        for (int idx = tid; idx < 4096; idx += 128) {
            int ri = idx >> 7, k = idx & 127;
            float v = X[(size_t)(row0 + ri) * TDIM_ + kc + k];
            Xs[ri][k] = (v - mu_s[ri]) * rs_s[ri] * gam[kc + k] + bet[kc + k];
        }
        // W tile
        for (int idx = tid; idx < 4096; idx += 128) {
            int h = idx >> 7, k = idx & 127;
            Ws[h][k] = W[h * TDIM_ + kc + k];
        }
        __syncthreads();

        #pragma unroll 8
        for (int k = 0; k < 128; k++) {
            float a0 = Xs[r0][k];
            float a1 = Xs[r0 + 1][k];
            #pragma unroll
            for (int j = 0; j < 4; j++) {
                float w = Ws[h0 + j][k];
                acc[0][j] += a0 * w;
                acc[1][j] += a1 * w;
            }
        }
    }

    #pragma unroll
    for (int rr = 0; rr < 2; rr++) {
        int row = row0 + r0 + rr;
        float tm = tmask[row];
        float4 o;
        o.x = (acc[rr][0] + bt[h0 + 0]) * tm;
        o.y = (acc[rr][1] + bt[h0 + 1]) * tm;
        o.z = (acc[rr][2] + bt[h0 + 2]) * tm;
        o.w = (acc[rr][3] + bt[h0 + 3]) * tm;
        *reinterpret_cast<float4*>(&g_tf[row * HID_ + h0]) = o;
    }
}

// ---------------------------------------------------------------------------
// Kernel B: layernorm(drug) @ W_d^T + b_d, * dmask  ->  g_df [B*NA, 32]
// 256 blocks (one per row) x 128 threads.
// ---------------------------------------------------------------------------
__global__ void df_kernel(const float* __restrict__ X,
                          const float* __restrict__ dmask,
                          const float* __restrict__ gam,
                          const float* __restrict__ bet,
                          const float* __restrict__ W,
                          const float* __restrict__ bd)
{
    const int row = blockIdx.x;
    const int tid = threadIdx.x;
    __shared__ float xn[128];
    __shared__ float red[8];

    float v = X[row * DDIM_ + tid];
    float s = v, ss = v * v;
    for (int o = 16; o; o >>= 1) {
        s  += __shfl_xor_sync(0xffffffffu, s,  o);
        ss += __shfl_xor_sync(0xffffffffu, ss, o);
    }
    if ((tid & 31) == 0) { red[tid >> 5] = s; red[4 + (tid >> 5)] = ss; }
    __syncthreads();
    float sum = red[0] + red[1] + red[2] + red[3];
    float sq  = red[4] + red[5] + red[6] + red[7];
    float mu  = sum * (1.f / 128.f);
    float var = sq * (1.f / 128.f) - mu * mu;
    float rs  = rsqrtf(var + 1e-5f);
    xn[tid] = (v - mu) * rs * gam[tid] + bet[tid];
    __syncthreads();

    const int wid = tid >> 5, lane = tid & 31;
    const float dm = dmask[row];
    #pragma unroll
    for (int j = 0; j < 8; j++) {
        int h = wid * 8 + j;
        float acc = 0.f;
        #pragma unroll
        for (int q = 0; q < 4; q++)
            acc += xn[lane + q * 32] * W[h * DDIM_ + lane + q * 32];
        for (int o = 16; o; o >>= 1)
            acc += __shfl_xor_sync(0xffffffffu, acc, o);
        if (lane == 0) g_df[row * HID_ + h] = (acc + bd[h]) * dm;
    }
}

// ---------------------------------------------------------------------------
// Kernel C: G[b,m,i,c] = sum_e df[b,m,e] * W_out[i, c*32+e]
// grid (16 i-chunks of 8, 4 b) x 256 threads.
// ---------------------------------------------------------------------------
__global__ void g_kernel(const float* __restrict__ Wout)
{
    const int i0 = blockIdx.x * 8;
    const int b  = blockIdx.y;
    __shared__ float dfT[32][64];        // [e][m]
    __shared__ float Wc[8][1024];
    const int tid = threadIdx.x;

    for (int idx = tid; idx < 2048; idx += 256) {
        int e = idx >> 6, m = idx & 63;
        dfT[e][m] = g_df[(b * NA_ + m) * HID_ + e];
    }
    for (int idx = tid; idx < 8192; idx += 256) {
        int ii = idx >> 10, k = idx & 1023;
        Wc[ii][k] = Wout[(i0 + ii) * 1024 + k];
    }
    __syncthreads();

    const int m0 = (tid & 15) * 4;
    const int pr = tid >> 4;
    for (int it = 0; it < 16; it++) {
        int ic = it * 16 + pr;
        int i = ic >> 5, c = ic & 31;
        const float* wrow = &Wc[i][c * 32];
        float4 acc = {0.f, 0.f, 0.f, 0.f};
        #pragma unroll
        for (int e = 0; e < 32; e++) {
            float w = wrow[e];
            float4 d = *reinterpret_cast<const float4*>(&dfT[e][m0]);
            acc.x += w * d.x; acc.y += w * d.y;
            acc.z += w * d.z; acc.w += w * d.w;
        }
        size_t base = ((size_t)((b * NA_ + m0) * INTD_ + (i0 + i))) * HID_ + c;
        const size_t mstep = (size_t)INTD_ * HID_;   // 4096
        g_G[base]             = acc.x;
        g_G[base + mstep]     = acc.y;
        g_G[base + 2 * mstep] = acc.z;
        g_G[base + 3 * mstep] = acc.w;
    }
}

// ---------------------------------------------------------------------------
// Kernel D: main contraction with packed fp32x2 FMA.
//   out[b,n,m,i] = (sum_c tf[b,n,c]*G[b,m,i,c] + b_out[i]) * tmask[b,n]*dmask[b,m]
// grid (8 n-tiles, 64 m, 4 b) x 256 threads. Block tile 64n x 128i, K=32.
// Thread tile 8n x 4i; n-pairs packed into f32x2 lanes.
// ---------------------------------------------------------------------------
__global__ void __launch_bounds__(256) outer_kernel(
    const float* __restrict__ bout,
    const float* __restrict__ tmask,
    const float* __restrict__ dmask,
    float* __restrict__ out,
    float* __restrict__ mask_out)
{
    const int nt = blockIdx.x, m = blockIdx.y, b = blockIdx.z;
    const int nblk = nt * 64;

    __shared__ __align__(16) float tf_s[32][68];   // [c][n], padded
    __shared__ float G_s[32][132];                 // [c][i], padded
    __shared__ float bout_s[128];

    const int tid = threadIdx.x;

    for (int idx = tid; idx < 2048; idx += 256) {
        int n = idx >> 5, c = idx & 31;
        tf_s[c][n] = g_tf[(b * NR_ + nblk + n) * HID_ + c];
    }
    {
        const float* Gm = g_G + (size_t)(b * NA_ + m) * (INTD_ * HID_);
        for (int idx = tid; idx < 4096; idx += 256) {
            int i = idx >> 5, c = idx & 31;
            G_s[c][i] = Gm[idx];
        }
    }
    if (tid < 128) bout_s[tid] = bout[tid];
    __syncthreads();

    const int tn = tid >> 5;        // 0..7  -> n-group of 8
    const int ti = tid & 31;        // i base; i = ti + 32*j
    const int n0 = tn * 8;

    unsigned long long acc[4][4] = {};   // [n-pair p][i j] packed f32x2

    #pragma unroll
    for (int c = 0; c < 32; c++) {
        const ulonglong2 A0 = *reinterpret_cast<const ulonglong2*>(&tf_s[c][n0]);
        const ulonglong2 A1 = *reinterpret_cast<const ulonglong2*>(&tf_s[c][n0 + 4]);
        unsigned long long a[4];
        a[0] = A0.x; a[1] = A0.y; a[2] = A1.x; a[3] = A1.y;

        unsigned long long gg[4];
        #pragma unroll
        for (int j = 0; j < 4; j++) {
            unsigned gu = __float_as_uint(G_s[c][ti + 32 * j]);
            asm("mov.b64 %0, {%1, %1};" : "=l"(gg[j]) : "r"(gu));
        }
        #pragma unroll
        for (int p = 0; p < 4; p++) {
            #pragma unroll
            for (int j = 0; j < 4; j++) {
                asm("fma.rn.f32x2 %0, %1, %2, %0;"
                    : "+l"(acc[p][j]) : "l"(a[p]), "l"(gg[j]));
            }
        }
    }

    // epilogue: bias + mask + store (coalesced along i)
    const float dm = dmask[b * NA_ + m];
    #pragma unroll
    for (int p = 0; p < 4; p++) {
        const int n_lo = nblk + n0 + 2 * p;
        const float f_lo = tmask[b * NR_ + n_lo] * dm;
        const float f_hi = tmask[b * NR_ + n_lo + 1] * dm;
        const size_t base_lo = ((size_t)((b * NR_ + n_lo) * NA_ + m)) << 7;  // *128
        const size_t base_hi = base_lo + ((size_t)NA_ << 7);                  // next n
        #pragma unroll
        for (int j = 0; j < 4; j++) {
            unsigned rlo, rhi;
            asm("mov.b64 {%0, %1}, %2;" : "=r"(rlo), "=r"(rhi) : "l"(acc[p][j]));
            const int i = ti + 32 * j;
            out[base_lo + i] = (__uint_as_float(rlo) + bout_s[i]) * f_lo;
            out[base_hi + i] = (__uint_as_float(rhi) + bout_s[i]) * f_hi;
        }
    }

    // mask output (second tuple element), each (b,n,m) written exactly once
    if (mask_out != nullptr && tid < 64) {
        const int n = nblk + tid;
        mask_out[(size_t)(b * NR_ + n) * NA_ + m] = tmask[b * NR_ + n] * dm;
    }
}

// ---------------------------------------------------------------------------
// launch
// ---------------------------------------------------------------------------
extern "C" void kernel_launch(void* const* d_in, const int* in_sizes, int n_in,
                              void* d_out, int out_size)
{
    const float* target = (const float*)d_in[0];   // [4,512,1024]
    const float* drug   = (const float*)d_in[1];   // [4,64,128]
    const float* tmask  = (const float*)d_in[2];   // [4,512]
    const float* dmask  = (const float*)d_in[3];   // [4,64]
    const float* ln_t_g = (const float*)d_in[4];
    const float* ln_t_b = (const float*)d_in[5];
    const float* ln_d_g = (const float*)d_in[6];
    const float* ln_d_b = (const float*)d_in[7];
    const float* W_t    = (const float*)d_in[8];   // [32,1024]
    const float* b_t    = (const float*)d_in[9];
    const float* W_d    = (const float*)d_in[10];  // [32,128]
    const float* b_d    = (const float*)d_in[11];
    const float* W_out  = (const float*)d_in[12];  // [128,1024]
    const float* b_out  = (const float*)d_in[13];

    float* outer = (float*)d_out;
    const long long OUTER_ELEMS = (long long)B_ * NR_ * NA_ * INTD_;  // 16,777,216
    const long long MASK_ELEMS  = (long long)B_ * NR_ * NA_;          // 131,072
    float* maskp = (out_size >= (int)(OUTER_ELEMS + MASK_ELEMS))
                       ? outer + OUTER_ELEMS : nullptr;

    tf_kernel<<<64, 128>>>(target, tmask, ln_t_g, ln_t_b, W_t, b_t);
    df_kernel<<<256, 128>>>(drug, dmask, ln_d_g, ln_d_b, W_d, b_d);
    g_kernel<<<dim3(16, 4), 256>>>(W_out);
    outer_kernel<<<dim3(8, 64, 4), 256>>>(b_out, tmask, dmask, outer, maskp);
}

// round 17
// speedup vs baseline: 1.0342x; 1.0068x over previous
#include <cuda_runtime.h>
#include <cstdint>

// ---------------------------------------------------------------------------
// Problem constants
//   B=4, NR=512, NA=64, TDIM=1024, DDIM=128, HID=32, INT=128
//   outer: [B,NR,NA,INT] = 16,777,216 f32 ; mask: [B,NR,NA] = 131,072 f32
// ---------------------------------------------------------------------------
#define B_      4
#define NR_     512
#define NA_     64
#define TDIM_   1024
#define DDIM_   128
#define HID_    32
#define INTD_   128

// Scratch (allocation-free rule: __device__ globals)
__device__ float g_tf[B_ * NR_ * HID_];            // 65536
__device__ float g_df[B_ * NA_ * HID_];            // 8192
__device__ float g_G [B_ * NA_ * INTD_ * HID_];    // 1,048,576 (4 MB)

// ---------------------------------------------------------------------------
// Kernel A: layernorm(target) @ W_t^T + b_t, * tmask  ->  g_tf [B*NR, 32]
// 64 blocks x 128 threads; each block does 32 rows, K=1024 in 128-chunks.
// ---------------------------------------------------------------------------
__global__ void tf_kernel(const float* __restrict__ X,
                          const float* __restrict__ tmask,
                          const float* __restrict__ gam,
                          const float* __restrict__ bet,
                          const float* __restrict__ W,
                          const float* __restrict__ bt)
{
    __shared__ float mu_s[32], rs_s[32];
    __shared__ float Xs[32][129];
    __shared__ float Ws[32][129];

    const int tid  = threadIdx.x;      // 128
    const int lane = tid & 31;
    const int wid  = tid >> 5;         // 4 warps
    const int row0 = blockIdx.x * 32;

    // ---- per-row LN stats (each warp: 8 rows) ----
    for (int j = 0; j < 8; j++) {
        const int ri = wid * 8 + j;
        const float* xr = X + (size_t)(row0 + ri) * TDIM_;
        float s = 0.f, ss = 0.f;
        #pragma unroll 8
        for (int q = 0; q < 32; q++) {
            float v = xr[lane + q * 32];
            s += v; ss += v * v;
        }
        for (int o = 16; o; o >>= 1) {
            s  += __shfl_xor_sync(0xffffffffu, s,  o);
            ss += __shfl_xor_sync(0xffffffffu, ss, o);
        }
        if (lane == 0) {
            float m   = s * (1.f / 1024.f);
            float var = ss * (1.f / 1024.f) - m * m;
            mu_s[ri] = m;
            rs_s[ri] = rsqrtf(var + 1e-5f);
        }
    }
    __syncthreads();

    const int r0 = (tid >> 3) * 2;     // 0..30 step 2
    const int h0 = (tid & 7) * 4;      // 0..28 step 4
    float acc[2][4] = {};

    for (int kc = 0; kc < TDIM_; kc += 128) {
        __syncthreads();
        // normalized X tile (coalesced global, conflict-free STS)
        for (int idx = tid; idx < 4096; idx += 128) {
            int ri = idx >> 7, k = idx & 127;
            float v = X[(size_t)(row0 + ri) * TDIM_ + kc + k];
            Xs[ri][k] = (v - mu_s[ri]) * rs_s[ri] * gam[kc + k] + bet[kc + k];
        }
        // W tile
        for (int idx = tid; idx < 4096; idx += 128) {
            int h = idx >> 7, k = idx & 127;
            Ws[h][k] = W[h * TDIM_ + kc + k];
        }
        __syncthreads();

        #pragma unroll 8
        for (int k = 0; k < 128; k++) {
            float a0 = Xs[r0][k];
            float a1 = Xs[r0 + 1][k];
            #pragma unroll
            for (int j = 0; j < 4; j++) {
                float w = Ws[h0 + j][k];
                acc[0][j] += a0 * w;
                acc[1][j] += a1 * w;
            }
        }
    }

    #pragma unroll
    for (int rr = 0; rr < 2; rr++) {
        int row = row0 + r0 + rr;
        float tm = tmask[row];
        float4 o;
        o.x = (acc[rr][0] + bt[h0 + 0]) * tm;
        o.y = (acc[rr][1] + bt[h0 + 1]) * tm;
        o.z = (acc[rr][2] + bt[h0 + 2]) * tm;
        o.w = (acc[rr][3] + bt[h0 + 3]) * tm;
        *reinterpret_cast<float4*>(&g_tf[row * HID_ + h0]) = o;
    }
}

// ---------------------------------------------------------------------------
// Kernel B: layernorm(drug) @ W_d^T + b_d, * dmask  ->  g_df [B*NA, 32]
// 256 blocks (one per row) x 128 threads.
// ---------------------------------------------------------------------------
__global__ void df_kernel(const float* __restrict__ X,
                          const float* __restrict__ dmask,
                          const float* __restrict__ gam,
                          const float* __restrict__ bet,
                          const float* __restrict__ W,
                          const float* __restrict__ bd)
{
    const int row = blockIdx.x;
    const int tid = threadIdx.x;
    __shared__ float xn[128];
    __shared__ float red[8];

    float v = X[row * DDIM_ + tid];
    float s = v, ss = v * v;
    for (int o = 16; o; o >>= 1) {
        s  += __shfl_xor_sync(0xffffffffu, s,  o);
        ss += __shfl_xor_sync(0xffffffffu, ss, o);
    }
    if ((tid & 31) == 0) { red[tid >> 5] = s; red[4 + (tid >> 5)] = ss; }
    __syncthreads();
    float sum = red[0] + red[1] + red[2] + red[3];
    float sq  = red[4] + red[5] + red[6] + red[7];
    float mu  = sum * (1.f / 128.f);
    float var = sq * (1.f / 128.f) - mu * mu;
    float rs  = rsqrtf(var + 1e-5f);
    xn[tid] = (v - mu) * rs * gam[tid] + bet[tid];
    __syncthreads();

    const int wid = tid >> 5, lane = tid & 31;
    const float dm = dmask[row];
    #pragma unroll
    for (int j = 0; j < 8; j++) {
        int h = wid * 8 + j;
        float acc = 0.f;
        #pragma unroll
        for (int q = 0; q < 4; q++)
            acc += xn[lane + q * 32] * W[h * DDIM_ + lane + q * 32];
        for (int o = 16; o; o >>= 1)
            acc += __shfl_xor_sync(0xffffffffu, acc, o);
        if (lane == 0) g_df[row * HID_ + h] = (acc + bd[h]) * dm;
    }
}

// ---------------------------------------------------------------------------
// Kernel C: G[b,m,i,c] = sum_e df[b,m,e] * W_out[i, c*32+e]
// grid (16 i-chunks of 8, 4 b) x 256 threads.
// ---------------------------------------------------------------------------
__global__ void g_kernel(const float* __restrict__ Wout)
{
    const int i0 = blockIdx.x * 8;
    const int b  = blockIdx.y;
    __shared__ float dfT[32][64];        // [e][m]
    __shared__ float Wc[8][1024];
    const int tid = threadIdx.x;

    for (int idx = tid; idx < 2048; idx += 256) {
        int e = idx >> 6, m = idx & 63;
        dfT[e][m] = g_df[(b * NA_ + m) * HID_ + e];
    }
    for (int idx = tid; idx < 8192; idx += 256) {
        int ii = idx >> 10, k = idx & 1023;
        Wc[ii][k] = Wout[(i0 + ii) * 1024 + k];
    }
    __syncthreads();

    const int m0 = (tid & 15) * 4;
    const int pr = tid >> 4;
    for (int it = 0; it < 16; it++) {
        int ic = it * 16 + pr;
        int i = ic >> 5, c = ic & 31;
        const float* wrow = &Wc[i][c * 32];
        float4 acc = {0.f, 0.f, 0.f, 0.f};
        #pragma unroll
        for (int e = 0; e < 32; e++) {
            float w = wrow[e];
            float4 d = *reinterpret_cast<const float4*>(&dfT[e][m0]);
            acc.x += w * d.x; acc.y += w * d.y;
            acc.z += w * d.z; acc.w += w * d.w;
        }
        size_t base = ((size_t)((b * NA_ + m0) * INTD_ + (i0 + i))) * HID_ + c;
        const size_t mstep = (size_t)INTD_ * HID_;   // 4096
        g_G[base]             = acc.x;
        g_G[base + mstep]     = acc.y;
        g_G[base + 2 * mstep] = acc.z;
        g_G[base + 3 * mstep] = acc.w;
    }
}

// ---------------------------------------------------------------------------
// Kernel D: main contraction with packed fp32x2 FMA.
//   out[b,n,m,i] = (sum_c tf[b,n,c]*G[b,m,i,c] + b_out[i]) * tmask[b,n]*dmask[b,m]
// grid (8 n-tiles, 64 m, 4 b) x 256 threads. Block tile 64n x 128i, K=32.
// Thread tile 8n x 4i; n-pairs packed into f32x2 lanes.
// ---------------------------------------------------------------------------
__global__ void __launch_bounds__(256) outer_kernel(
    const float* __restrict__ bout,
    const float* __restrict__ tmask,
    const float* __restrict__ dmask,
    float* __restrict__ out,
    float* __restrict__ mask_out)
{
    const int nt = blockIdx.x, m = blockIdx.y, b = blockIdx.z;
    const int nblk = nt * 64;

    __shared__ __align__(16) float tf_s[32][68];   // [c][n], padded
    __shared__ float G_s[32][132];                 // [c][i], padded
    __shared__ float bout_s[128];

    const int tid = threadIdx.x;

    for (int idx = tid; idx < 2048; idx += 256) {
        int n = idx >> 5, c = idx & 31;
        tf_s[c][n] = g_tf[(b * NR_ + nblk + n) * HID_ + c];
    }
    {
        const float* Gm = g_G + (size_t)(b * NA_ + m) * (INTD_ * HID_);
        for (int idx = tid; idx < 4096; idx += 256) {
            int i = idx >> 5, c = idx & 31;
            G_s[c][i] = Gm[idx];
        }
    }
    if (tid < 128) bout_s[tid] = bout[tid];
    __syncthreads();

    const int tn = tid >> 5;        // 0..7  -> n-group of 8
    const int ti = tid & 31;        // i base; i = ti + 32*j
    const int n0 = tn * 8;

    unsigned long long acc[4][4] = {};   // [n-pair p][i j] packed f32x2

    #pragma unroll
    for (int c = 0; c < 32; c++) {
        const ulonglong2 A0 = *reinterpret_cast<const ulonglong2*>(&tf_s[c][n0]);
        const ulonglong2 A1 = *reinterpret_cast<const ulonglong2*>(&tf_s[c][n0 + 4]);
        unsigned long long a[4];
        a[0] = A0.x; a[1] = A0.y; a[2] = A1.x; a[3] = A1.y;

        unsigned long long gg[4];
        #pragma unroll
        for (int j = 0; j < 4; j++) {
            unsigned gu = __float_as_uint(G_s[c][ti + 32 * j]);
            asm("mov.b64 %0, {%1, %1};" : "=l"(gg[j]) : "r"(gu));
        }
        #pragma unroll
        for (int p = 0; p < 4; p++) {
            #pragma unroll
            for (int j = 0; j < 4; j++) {
                asm("fma.rn.f32x2 %0, %1, %2, %0;"
                    : "+l"(acc[p][j]) : "l"(a[p]), "l"(gg[j]));
            }
        }
    }

    // epilogue: bias + mask + store (coalesced along i)
    const float dm = dmask[b * NA_ + m];
    #pragma unroll
    for (int p = 0; p < 4; p++) {
        const int n_lo = nblk + n0 + 2 * p;
        const float f_lo = tmask[b * NR_ + n_lo] * dm;
        const float f_hi = tmask[b * NR_ + n_lo + 1] * dm;
        const size_t base_lo = ((size_t)((b * NR_ + n_lo) * NA_ + m)) << 7;  // *128
        const size_t base_hi = base_lo + ((size_t)NA_ << 7);                  // next n
        #pragma unroll
        for (int j = 0; j < 4; j++) {
            unsigned rlo, rhi;
            asm("mov.b64 {%0, %1}, %2;" : "=r"(rlo), "=r"(rhi) : "l"(acc[p][j]));
            const int i = ti + 32 * j;
            out[base_lo + i] = (__uint_as_float(rlo) + bout_s[i]) * f_lo;
            out[base_hi + i] = (__uint_as_float(rhi) + bout_s[i]) * f_hi;
        }
    }

    // mask output (second tuple element), each (b,n,m) written exactly once
    if (mask_out != nullptr && tid < 64) {
        const int n = nblk + tid;
        mask_out[(size_t)(b * NR_ + n) * NA_ + m] = tmask[b * NR_ + n] * dm;
    }
}

// ---------------------------------------------------------------------------
// launch
// ---------------------------------------------------------------------------
extern "C" void kernel_launch(void* const* d_in, const int* in_sizes, int n_in,
                              void* d_out, int out_size)
{
    const float* target = (const float*)d_in[0];   // [4,512,1024]
    const float* drug   = (const float*)d_in[1];   // [4,64,128]
    const float* tmask  = (const float*)d_in[2];   // [4,512]
    const float* dmask  = (const float*)d_in[3];   // [4,64]
    const float* ln_t_g = (const float*)d_in[4];
    const float* ln_t_b = (const float*)d_in[5];
    const float* ln_d_g = (const float*)d_in[6];
    const float* ln_d_b = (const float*)d_in[7];
    const float* W_t    = (const float*)d_in[8];   // [32,1024]
    const float* b_t    = (const float*)d_in[9];
    const float* W_d    = (const float*)d_in[10];  // [32,128]
    const float* b_d    = (const float*)d_in[11];
    const float* W_out  = (const float*)d_in[12];  // [128,1024]
    const float* b_out  = (const float*)d_in[13];

    float* outer = (float*)d_out;
    const long long OUTER_ELEMS = (long long)B_ * NR_ * NA_ * INTD_;  // 16,777,216
    const long long MASK_ELEMS  = (long long)B_ * NR_ * NA_;          // 131,072
    float* maskp = (out_size >= (int)(OUTER_ELEMS + MASK_ELEMS))
                       ? outer + OUTER_ELEMS : nullptr;

    tf_kernel<<<64, 128>>>(target, tmask, ln_t_g, ln_t_b, W_t, b_t);
    df_kernel<<<256, 128>>>(drug, dmask, ln_d_g, ln_d_b, W_d, b_d);
    g_kernel<<<dim3(16, 4), 256>>>(W_out);
    outer_kernel<<<dim3(8, 64, 4), 256>>>(b_out, tmask, dmask, outer, maskp);
}